// round 9
// baseline (speedup 1.0000x reference)
#include <cuda_runtime.h>
#include <cuda_fp16.h>
#include <cstdint>

// ---------------- problem constants ----------------
static constexpr int TOKENS = 4096;
static constexpr int IN_F   = 4096;
static constexpr int OUT_F  = 11008;
static constexpr int G      = 704512;   // OUT_F*IN_F/64
static constexpr int RHALF  = 32;       // GS/2
static constexpr int A_DIM  = 172;      // G / IN_F

// ---------------- GEMM tiling ----------------
static constexpr int M_TILE = 128;
static constexpr int N_TILE = 256;
static constexpr int K_TILE = 64;
static constexpr int K_ITERS = IN_F / K_TILE;              // 64
static constexpr int STAGES = 4;
static constexpr int A_TILE_BYTES = M_TILE * K_TILE * 2;   // 16384
static constexpr int B_TILE_BYTES = N_TILE * K_TILE * 2;   // 32768
static constexpr int STAGE_BYTES  = A_TILE_BYTES + B_TILE_BYTES;   // 49152
static constexpr int SMEM_DYN     = STAGES * STAGE_BYTES + 1024;   // 197632

static constexpr int M_TILES = TOKENS / M_TILE;   // 32
static constexpr int N_TILES = OUT_F / N_TILE;    // 43

static constexpr int NWARPS = 8;                  // 2x4 warp grid, 64x64 warp tiles

// ---------------- scratch (device globals: allocation-free) ----------------
// Pre-tiled, pre-SW128-swizzled layouts:
//  X tiles: [m_tile(32)][kt(64)] blocks of 16384B: 128 rows x 128B, swizzled
//  W tiles: [n_tile(43)][kt(64)] blocks of 32768B: 256 rows x 128B, swizzled
__device__ __half d_Xt[(size_t)TOKENS * IN_F];
__device__ __half d_Wt[(size_t)OUT_F * IN_F];

// ---------------- small PTX helpers ----------------
__device__ __forceinline__ uint32_t smem_u32(const void* p) {
    uint32_t a;
    asm("{ .reg .u64 t; cvta.to.shared.u64 t, %1; cvt.u32.u64 %0, t; }" : "=r"(a) : "l"(p));
    return a;
}

#define MBARRIER_INIT(addr, cnt) \
    asm volatile("mbarrier.init.shared.b64 [%0], %1;" :: "r"(addr), "r"(cnt) : "memory")
#define MBARRIER_EXPECT_TX(addr, bytes) \
    asm volatile("mbarrier.arrive.expect_tx.shared.b64 _, [%0], %1;" :: "r"(addr), "r"(bytes) : "memory")
#define MBARRIER_ARRIVE(addr) \
    asm volatile("mbarrier.arrive.shared.b64 _, [%0];" :: "r"(addr) : "memory")

__device__ __forceinline__ void mbar_wait(uint32_t mbar, uint32_t parity) {
    uint32_t done = 0;
    while (!done) {
        asm volatile(
            "{\n\t.reg .pred p;\n\t"
            "mbarrier.try_wait.parity.shared::cta.b64 p, [%1], %2;\n\t"
            "selp.b32 %0, 1, 0, p;\n\t}"
            : "=r"(done) : "r"(mbar), "r"(parity) : "memory");
    }
}

// 1-D bulk copy gmem -> smem with mbarrier complete_tx (no tensormap needed)
__device__ __forceinline__ void bulk_g2s(uint32_t dst_smem, const void* src, uint32_t bytes, uint32_t mbar) {
    asm volatile(
        "cp.async.bulk.shared::cluster.global.mbarrier::complete_tx::bytes [%0], [%1], %2, [%3];"
        :: "r"(dst_smem), "l"(src), "r"(bytes), "r"(mbar) : "memory");
}

__device__ __forceinline__ void ldsm4(uint32_t r[4], uint32_t addr) {
    asm volatile("ldmatrix.sync.aligned.m8n8.x4.shared.b16 {%0,%1,%2,%3}, [%4];"
        : "=r"(r[0]), "=r"(r[1]), "=r"(r[2]), "=r"(r[3]) : "r"(addr));
}

__device__ __forceinline__ void mma16816(float c[4], const uint32_t a[4], uint32_t b0, uint32_t b1) {
    asm volatile(
        "mma.sync.aligned.m16n8k16.row.col.f32.f16.f16.f32 "
        "{%0,%1,%2,%3}, {%4,%5,%6,%7}, {%8,%9}, {%0,%1,%2,%3};"
        : "+f"(c[0]), "+f"(c[1]), "+f"(c[2]), "+f"(c[3])
        : "r"(a[0]), "r"(a[1]), "r"(a[2]), "r"(a[3]), "r"(b0), "r"(b1));
}

__device__ __forceinline__ uint32_t sw128(uint32_t off) { return off ^ ((off >> 3) & 0x70); }

union H8 { __half h[8]; uint4 u; };

// ---------------- kernel 1: x fp32 -> fp16, tiled+swizzled ----------------
__global__ void convert_x_kernel(const float* __restrict__ x) {
    int id = blockIdx.x * 256 + threadIdx.x;      // 2,097,152 total
    int t = id >> 9;                // token
    int k = (id & 511) << 3;        // 8 consecutive k
    const float4* xp = reinterpret_cast<const float4*>(x + (size_t)t * IN_F + k);
    float4 x0 = xp[0], x1 = xp[1];
    H8 v;
    v.h[0] = __float2half_rn(x0.x); v.h[1] = __float2half_rn(x0.y);
    v.h[2] = __float2half_rn(x0.z); v.h[3] = __float2half_rn(x0.w);
    v.h[4] = __float2half_rn(x1.x); v.h[5] = __float2half_rn(x1.y);
    v.h[6] = __float2half_rn(x1.z); v.h[7] = __float2half_rn(x1.w);
    int m = t >> 7, rt = t & 127, kt = k >> 6, col = k & 63;
    uint32_t off = sw128((uint32_t)(rt * 128 + col * 2));
    *reinterpret_cast<uint4*>(reinterpret_cast<char*>(d_Xt)
        + (((size_t)(m * 64 + kt)) << 14) + off) = v.u;
}

// ---------------- kernel 2: dequant W_q -> fp16, tiled+swizzled ----------------
__device__ __forceinline__ void store_w8(int o, int kt, int col, const uint4& val) {
    int n = o >> 8, rt = o & 255;
    uint32_t off = sw128((uint32_t)(rt * 128 + col * 2));
    *reinterpret_cast<uint4*>(reinterpret_cast<char*>(d_Wt)
        + (((size_t)(n * 64 + kt)) << 15) + off) = val;
}

__global__ void dequant_w_kernel(const int* __restrict__ Wq,
                                 const float* __restrict__ scale,
                                 const float* __restrict__ zero) {
    int r  = blockIdx.y;                              // 0..31
    int gb = blockIdx.x * blockDim.x + threadIdx.x;   // 0..88063
    int g  = gb << 3;                                 // 8 consecutive groups
    const int4* qp = reinterpret_cast<const int4*>(Wq + (size_t)r * G + g);
    int4 q0 = qp[0], q1 = qp[1];
    float4 s0 = *reinterpret_cast<const float4*>(scale + g);
    float4 s1 = *reinterpret_cast<const float4*>(scale + g + 4);
    float4 z0 = *reinterpret_cast<const float4*>(zero + g);
    float4 z1 = *reinterpret_cast<const float4*>(zero + g + 4);

    int v[8] = {q0.x, q0.y, q0.z, q0.w, q1.x, q1.y, q1.z, q1.w};
    float ss[8] = {s0.x, s0.y, s0.z, s0.w, s1.x, s1.y, s1.z, s1.w};
    float zz[8] = {z0.x, z0.y, z0.z, z0.w, z1.x, z1.y, z1.z, z1.w};

    H8 hi, lo;
#pragma unroll
    for (int j = 0; j < 8; j++) {
        float h = (float)((v[j] >> 4) & 0xF);
        float l = (float)(v[j] & 0xF);
        hi.h[j] = __float2half_rn((h - zz[j]) * ss[j]);
        lo.h[j] = __float2half_rn((l - zz[j]) * ss[j]);
    }
    int a = g >> 12, b = g & 4095;
    int o_hi = r * A_DIM + a;
    int o_lo = o_hi + RHALF * A_DIM;   // +5504
    int kt = b >> 6, col = b & 63;
    store_w8(o_hi, kt, col, hi.u);
    store_w8(o_lo, kt, col, lo.u);
}

// ---------------- kernel 3: HMMA fp16 GEMM + bias ----------------
// 256 threads = 8 warps in a 2x4 grid; each warp owns a 64x64 accumulator patch
// (128 fp32 regs). Explicit double-buffered A/B fragments across ks steps
// (prefetch ks+1 during ks MMAs) + empty-arrival hoisted to right after the
// last ldsm (smem reads done), giving the producer a head start.
__global__ void __launch_bounds__(256, 1)
gemm_kernel(float* __restrict__ out, const float* __restrict__ bias) {
    extern __shared__ __align__(1024) char dynsm[];
    __shared__ __align__(8) unsigned long long bars[2 * STAGES];  // [0..3] full, [4..7] empty

    const int tid = threadIdx.x;
    const int wid = tid >> 5, lane = tid & 31;
    const int warp_m = wid >> 2;       // 0..1  (64 rows each)
    const int warp_n = wid & 3;        // 0..3  (64 cols each)

    const int mt = blockIdx.x;       // fastest-varying -> one wave covers all M tiles
    const int nt = blockIdx.y;       // (L2-friendly: X panel stays resident)

    uint32_t base = (smem_u32(dynsm) + 1023u) & ~1023u;
    uint32_t bar0 = smem_u32(&bars[0]);

    if (tid == 0) {
#pragma unroll
        for (int s = 0; s < STAGES; s++) {
            MBARRIER_INIT(bar0 + 8 * s, 1);                   // full: tx-based
            MBARRIER_INIT(bar0 + 8 * (STAGES + s), NWARPS);   // empty: one arrive per warp
        }
        asm volatile("fence.proxy.async.shared::cta;" ::: "memory");
    }
    __syncthreads();

    const char* gA = reinterpret_cast<const char*>(d_Xt)
                   + ((size_t)mt * K_ITERS) * (size_t)A_TILE_BYTES;
    const char* gB = reinterpret_cast<const char*>(d_Wt)
                   + ((size_t)nt * K_ITERS) * (size_t)B_TILE_BYTES;

    // prologue: fill all stages
    if (tid == 0) {
#pragma unroll
        for (int j = 0; j < STAGES; j++) {
            uint32_t full = bar0 + 8 * j;
            MBARRIER_EXPECT_TX(full, (uint32_t)STAGE_BYTES);
            bulk_g2s(base + j * STAGE_BYTES,                gA + (size_t)j * A_TILE_BYTES, A_TILE_BYTES, full);
            bulk_g2s(base + j * STAGE_BYTES + A_TILE_BYTES, gB + (size_t)j * B_TILE_BYTES, B_TILE_BYTES, full);
        }
    }

    // per-thread ldmatrix address components (SW128 xor collapses to a constant)
    const int a_row = warp_m * 64 + (lane & 15);
    const uint32_t a_rowoff = (uint32_t)a_row * 128;
    const uint32_t a_xor = (uint32_t)(a_row & 7) << 4;
    const uint32_t a_kc  = (uint32_t)(lane >> 4) << 4;      // 0 or 16 bytes

    const int b_row = warp_n * 64 + ((lane >> 4) << 3) + (lane & 7);
    const uint32_t b_rowoff = (uint32_t)b_row * 128;
    const uint32_t b_xor = (uint32_t)(b_row & 7) << 4;
    const uint32_t b_kc  = (uint32_t)((lane >> 3) & 1) << 4;

    float acc[4][8][4];    // 4 m16 blocks x 8 n8 blocks x 4 regs = 128 regs
#pragma unroll
    for (int i = 0; i < 4; i++)
#pragma unroll
        for (int j = 0; j < 8; j++)
#pragma unroll
            for (int q = 0; q < 4; q++) acc[i][j][q] = 0.0f;

    int s = 0;
    uint32_t phase = 0;
#pragma unroll 1
    for (int kt = 0; kt < K_ITERS; kt++) {
        mbar_wait(bar0 + 8 * s, phase);
        uint32_t As = base + s * STAGE_BYTES;
        uint32_t Bs = As + A_TILE_BYTES;

        uint32_t aF[2][4][4], bF[2][4][4];
        // load ks=0 fragments
#pragma unroll
        for (int mb = 0; mb < 4; mb++)
            ldsm4(aF[0][mb], As + a_rowoff + mb * 2048 + ((0 + a_kc) ^ a_xor));
#pragma unroll
        for (int pb = 0; pb < 4; pb++)
            ldsm4(bF[0][pb], Bs + b_rowoff + pb * 2048 + ((0 + b_kc) ^ b_xor));

#pragma unroll
        for (int ks = 0; ks < 4; ks++) {
            const int cur = ks & 1, nxt = cur ^ 1;
            if (ks < 3) {
                const uint32_t kb = (uint32_t)(ks + 1) * 32;
#pragma unroll
                for (int mb = 0; mb < 4; mb++)
                    ldsm4(aF[nxt][mb], As + a_rowoff + mb * 2048 + ((kb + a_kc) ^ a_xor));
#pragma unroll
                for (int pb = 0; pb < 4; pb++)
                    ldsm4(bF[nxt][pb], Bs + b_rowoff + pb * 2048 + ((kb + b_kc) ^ b_xor));
            } else {
                // all smem reads for this stage are done -> free it for the producer
                if (lane == 0) MBARRIER_ARRIVE(bar0 + 8 * (STAGES + s));
            }
#pragma unroll
            for (int pb = 0; pb < 4; pb++) {
#pragma unroll
                for (int mb = 0; mb < 4; mb++) {
                    mma16816(acc[mb][2 * pb],     aF[cur][mb], bF[cur][pb][0], bF[cur][pb][1]);
                    mma16816(acc[mb][2 * pb + 1], aF[cur][mb], bF[cur][pb][2], bF[cur][pb][3]);
                }
            }
        }
        // producer: tid 0 waits for all warps, then refills this stage
        if (tid == 0 && kt + STAGES < K_ITERS) {
            mbar_wait(bar0 + 8 * (STAGES + s), phase);
            int j = kt + STAGES;
            uint32_t full = bar0 + 8 * s;
            MBARRIER_EXPECT_TX(full, (uint32_t)STAGE_BYTES);
            bulk_g2s(base + s * STAGE_BYTES,                gA + (size_t)j * A_TILE_BYTES, A_TILE_BYTES, full);
            bulk_g2s(base + s * STAGE_BYTES + A_TILE_BYTES, gB + (size_t)j * B_TILE_BYTES, B_TILE_BYTES, full);
        }
        if (++s == STAGES) { s = 0; phase ^= 1; }
    }

    // ---- epilogue: direct register -> gmem with bias ----
    const int m0 = mt * M_TILE;
    const int n0 = nt * N_TILE;
    const int col = n0 + warp_n * 64 + (lane & 3) * 2;

    float2 bb[8];
#pragma unroll
    for (int nf = 0; nf < 8; nf++)
        bb[nf] = *reinterpret_cast<const float2*>(bias + col + nf * 8);

#pragma unroll
    for (int mb = 0; mb < 4; mb++) {
        const int r0 = m0 + warp_m * 64 + mb * 16 + (lane >> 2);
        float* p0 = out + (size_t)r0 * OUT_F;
        float* p1 = p0 + (size_t)8 * OUT_F;
#pragma unroll
        for (int nf = 0; nf < 8; nf++) {
            float2 v0, v1;
            v0.x = acc[mb][nf][0] + bb[nf].x;
            v0.y = acc[mb][nf][1] + bb[nf].y;
            v1.x = acc[mb][nf][2] + bb[nf].x;
            v1.y = acc[mb][nf][3] + bb[nf].y;
            *reinterpret_cast<float2*>(p0 + col + nf * 8) = v0;
            *reinterpret_cast<float2*>(p1 + col + nf * 8) = v1;
        }
    }
}

// ---------------- launch ----------------
extern "C" void kernel_launch(void* const* d_in, const int* in_sizes, int n_in,
                              void* d_out, int out_size) {
    const float* x     = (const float*)d_in[0];
    const int*   Wq    = (const int*)  d_in[1];
    const float* scale = (const float*)d_in[2];
    const float* zero  = (const float*)d_in[3];
    const float* bias  = (const float*)d_in[4];
    float* out = (float*)d_out;

    convert_x_kernel<<<(TOKENS * IN_F / 8) / 256, 256>>>(x);
    dequant_w_kernel<<<dim3((G / 8) / 256, RHALF), 256>>>(Wq, scale, zero);

    cudaFuncSetAttribute(gemm_kernel, cudaFuncAttributeMaxDynamicSharedMemorySize, SMEM_DYN);
    gemm_kernel<<<dim3(M_TILES, N_TILES), 256, SMEM_DYN>>>(out, bias);
}

// round 10
// speedup vs baseline: 1.0556x; 1.0556x over previous
#include <cuda_runtime.h>
#include <cuda_fp16.h>
#include <cstdint>

// ---------------- problem constants ----------------
static constexpr int TOKENS = 4096;
static constexpr int IN_F   = 4096;
static constexpr int OUT_F  = 11008;
static constexpr int G      = 704512;   // OUT_F*IN_F/64
static constexpr int RHALF  = 32;       // GS/2
static constexpr int A_DIM  = 172;      // G / IN_F

// ---------------- GEMM tiling ----------------
static constexpr int M_TILE = 128;
static constexpr int N_TILE = 128;
static constexpr int K_TILE = 64;
static constexpr int K_ITERS = IN_F / K_TILE;              // 64
static constexpr int STAGES = 3;
static constexpr int A_TILE_BYTES = M_TILE * K_TILE * 2;   // 16384
static constexpr int B_TILE_BYTES = N_TILE * K_TILE * 2;   // 16384
static constexpr int STAGE_BYTES  = A_TILE_BYTES + B_TILE_BYTES;   // 32768
static constexpr int SMEM_DYN     = STAGES * STAGE_BYTES + 1024;   // 99328 (2 CTAs/SM -> 198656)

static constexpr int M_TILES = TOKENS / M_TILE;   // 32
static constexpr int N_TILES = OUT_F / N_TILE;    // 86

static constexpr int NWARPS = 4;                  // 2x2 warp grid, 64x64 warp tiles

// ---------------- scratch (device globals: allocation-free) ----------------
// Pre-tiled, pre-SW128-swizzled layouts:
//  X tiles: [m_tile(32)][kt(64)] blocks of 16384B: 128 rows x 128B, swizzled
//  W tiles: [n_tile(86)][kt(64)] blocks of 16384B: 128 rows x 128B, swizzled
__device__ __half d_Xt[(size_t)TOKENS * IN_F];
__device__ __half d_Wt[(size_t)OUT_F * IN_F];

// ---------------- small PTX helpers ----------------
__device__ __forceinline__ uint32_t smem_u32(const void* p) {
    uint32_t a;
    asm("{ .reg .u64 t; cvta.to.shared.u64 t, %1; cvt.u32.u64 %0, t; }" : "=r"(a) : "l"(p));
    return a;
}

#define MBARRIER_INIT(addr, cnt) \
    asm volatile("mbarrier.init.shared.b64 [%0], %1;" :: "r"(addr), "r"(cnt) : "memory")
#define MBARRIER_EXPECT_TX(addr, bytes) \
    asm volatile("mbarrier.arrive.expect_tx.shared.b64 _, [%0], %1;" :: "r"(addr), "r"(bytes) : "memory")
#define MBARRIER_ARRIVE(addr) \
    asm volatile("mbarrier.arrive.shared.b64 _, [%0];" :: "r"(addr) : "memory")

__device__ __forceinline__ void mbar_wait(uint32_t mbar, uint32_t parity) {
    uint32_t done = 0;
    while (!done) {
        asm volatile(
            "{\n\t.reg .pred p;\n\t"
            "mbarrier.try_wait.parity.shared::cta.b64 p, [%1], %2;\n\t"
            "selp.b32 %0, 1, 0, p;\n\t}"
            : "=r"(done) : "r"(mbar), "r"(parity) : "memory");
    }
}

// 1-D bulk copy gmem -> smem with mbarrier complete_tx (no tensormap needed)
__device__ __forceinline__ void bulk_g2s(uint32_t dst_smem, const void* src, uint32_t bytes, uint32_t mbar) {
    asm volatile(
        "cp.async.bulk.shared::cluster.global.mbarrier::complete_tx::bytes [%0], [%1], %2, [%3];"
        :: "r"(dst_smem), "l"(src), "r"(bytes), "r"(mbar) : "memory");
}

__device__ __forceinline__ void ldsm4(uint32_t r[4], uint32_t addr) {
    asm volatile("ldmatrix.sync.aligned.m8n8.x4.shared.b16 {%0,%1,%2,%3}, [%4];"
        : "=r"(r[0]), "=r"(r[1]), "=r"(r[2]), "=r"(r[3]) : "r"(addr));
}

__device__ __forceinline__ void mma16816(float c[4], const uint32_t a[4], uint32_t b0, uint32_t b1) {
    asm volatile(
        "mma.sync.aligned.m16n8k16.row.col.f32.f16.f16.f32 "
        "{%0,%1,%2,%3}, {%4,%5,%6,%7}, {%8,%9}, {%0,%1,%2,%3};"
        : "+f"(c[0]), "+f"(c[1]), "+f"(c[2]), "+f"(c[3])
        : "r"(a[0]), "r"(a[1]), "r"(a[2]), "r"(a[3]), "r"(b0), "r"(b1));
}

__device__ __forceinline__ uint32_t sw128(uint32_t off) { return off ^ ((off >> 3) & 0x70); }

union H8 { __half h[8]; uint4 u; };

// ---------------- kernel 1: x fp32 -> fp16, tiled+swizzled ----------------
__global__ void convert_x_kernel(const float* __restrict__ x) {
    int id = blockIdx.x * 256 + threadIdx.x;      // 2,097,152 total
    int t = id >> 9;                // token
    int k = (id & 511) << 3;        // 8 consecutive k
    const float4* xp = reinterpret_cast<const float4*>(x + (size_t)t * IN_F + k);
    float4 x0 = xp[0], x1 = xp[1];
    H8 v;
    v.h[0] = __float2half_rn(x0.x); v.h[1] = __float2half_rn(x0.y);
    v.h[2] = __float2half_rn(x0.z); v.h[3] = __float2half_rn(x0.w);
    v.h[4] = __float2half_rn(x1.x); v.h[5] = __float2half_rn(x1.y);
    v.h[6] = __float2half_rn(x1.z); v.h[7] = __float2half_rn(x1.w);
    int m = t >> 7, rt = t & 127, kt = k >> 6, col = k & 63;
    uint32_t off = sw128((uint32_t)(rt * 128 + col * 2));
    *reinterpret_cast<uint4*>(reinterpret_cast<char*>(d_Xt)
        + (((size_t)(m * 64 + kt)) << 14) + off) = v.u;
}

// ---------------- kernel 2: dequant W_q -> fp16, tiled+swizzled ----------------
// W tiles are 128 rows x 64 cols fp16 (16384B), [n_tile(86)][kt(64)] order.
__device__ __forceinline__ void store_w8(int o, int kt, int col, const uint4& val) {
    int n = o >> 7, rt = o & 127;
    uint32_t off = sw128((uint32_t)(rt * 128 + col * 2));
    *reinterpret_cast<uint4*>(reinterpret_cast<char*>(d_Wt)
        + (((size_t)(n * 64 + kt)) << 14) + off) = val;
}

__global__ void dequant_w_kernel(const int* __restrict__ Wq,
                                 const float* __restrict__ scale,
                                 const float* __restrict__ zero) {
    int r  = blockIdx.y;                              // 0..31
    int gb = blockIdx.x * blockDim.x + threadIdx.x;   // 0..88063
    int g  = gb << 3;                                 // 8 consecutive groups
    const int4* qp = reinterpret_cast<const int4*>(Wq + (size_t)r * G + g);
    int4 q0 = qp[0], q1 = qp[1];
    float4 s0 = *reinterpret_cast<const float4*>(scale + g);
    float4 s1 = *reinterpret_cast<const float4*>(scale + g + 4);
    float4 z0 = *reinterpret_cast<const float4*>(zero + g);
    float4 z1 = *reinterpret_cast<const float4*>(zero + g + 4);

    int v[8] = {q0.x, q0.y, q0.z, q0.w, q1.x, q1.y, q1.z, q1.w};
    float ss[8] = {s0.x, s0.y, s0.z, s0.w, s1.x, s1.y, s1.z, s1.w};
    float zz[8] = {z0.x, z0.y, z0.z, z0.w, z1.x, z1.y, z1.z, z1.w};

    H8 hi, lo;
#pragma unroll
    for (int j = 0; j < 8; j++) {
        float h = (float)((v[j] >> 4) & 0xF);
        float l = (float)(v[j] & 0xF);
        hi.h[j] = __float2half_rn((h - zz[j]) * ss[j]);
        lo.h[j] = __float2half_rn((l - zz[j]) * ss[j]);
    }
    int a = g >> 12, b = g & 4095;
    int o_hi = r * A_DIM + a;
    int o_lo = o_hi + RHALF * A_DIM;   // +5504
    int kt = b >> 6, col = b & 63;
    store_w8(o_hi, kt, col, hi.u);
    store_w8(o_lo, kt, col, lo.u);
}

// ---------------- kernel 3: HMMA fp16 GEMM + bias ----------------
// 128 threads = 4 warps in a 2x2 grid; each warp owns a 64x64 accumulator patch
// (128 fp32 regs). 2 CTAs per SM (smaller 128x128 tiles): halves the wave-
// quantization tail and lets co-resident CTAs hide each other's bubbles.
// Sync = round-8 winner: per-stage full (tx) + empty (4-arrival) mbarriers,
// producer is tid 0, 3-stage pipeline.
__global__ void __launch_bounds__(128, 2)
gemm_kernel(float* __restrict__ out, const float* __restrict__ bias) {
    extern __shared__ __align__(1024) char dynsm[];
    __shared__ __align__(8) unsigned long long bars[2 * STAGES];  // full / empty

    const int tid = threadIdx.x;
    const int wid = tid >> 5, lane = tid & 31;
    const int warp_m = wid >> 1;       // 0..1  (64 rows each)
    const int warp_n = wid & 1;        // 0..1  (64 cols each)

    const int mt = blockIdx.x;       // fastest-varying -> one wave covers all M tiles
    const int nt = blockIdx.y;       // (L2-friendly: X panel stays resident)

    uint32_t base = (smem_u32(dynsm) + 1023u) & ~1023u;
    uint32_t bar0 = smem_u32(&bars[0]);

    if (tid == 0) {
#pragma unroll
        for (int s = 0; s < STAGES; s++) {
            MBARRIER_INIT(bar0 + 8 * s, 1);                   // full: tx-based
            MBARRIER_INIT(bar0 + 8 * (STAGES + s), NWARPS);   // empty: one arrive per warp
        }
        asm volatile("fence.proxy.async.shared::cta;" ::: "memory");
    }
    __syncthreads();

    const char* gA = reinterpret_cast<const char*>(d_Xt)
                   + ((size_t)mt * K_ITERS) * (size_t)A_TILE_BYTES;
    const char* gB = reinterpret_cast<const char*>(d_Wt)
                   + ((size_t)nt * K_ITERS) * (size_t)B_TILE_BYTES;

    // prologue: fill all stages
    if (tid == 0) {
#pragma unroll
        for (int j = 0; j < STAGES; j++) {
            uint32_t full = bar0 + 8 * j;
            MBARRIER_EXPECT_TX(full, (uint32_t)STAGE_BYTES);
            bulk_g2s(base + j * STAGE_BYTES,                gA + (size_t)j * A_TILE_BYTES, A_TILE_BYTES, full);
            bulk_g2s(base + j * STAGE_BYTES + A_TILE_BYTES, gB + (size_t)j * B_TILE_BYTES, B_TILE_BYTES, full);
        }
    }

    // per-thread ldmatrix address components (SW128 xor collapses to a constant)
    const int a_row = warp_m * 64 + (lane & 15);
    const uint32_t a_rowoff = (uint32_t)a_row * 128;
    const uint32_t a_xor = (uint32_t)(a_row & 7) << 4;
    const uint32_t a_kc  = (uint32_t)(lane >> 4) << 4;      // 0 or 16 bytes

    const int b_row = warp_n * 64 + ((lane >> 4) << 3) + (lane & 7);
    const uint32_t b_rowoff = (uint32_t)b_row * 128;
    const uint32_t b_xor = (uint32_t)(b_row & 7) << 4;
    const uint32_t b_kc  = (uint32_t)((lane >> 3) & 1) << 4;

    float acc[4][8][4];    // 4 m16 blocks x 8 n8 blocks x 4 regs = 128 regs
#pragma unroll
    for (int i = 0; i < 4; i++)
#pragma unroll
        for (int j = 0; j < 8; j++)
#pragma unroll
            for (int q = 0; q < 4; q++) acc[i][j][q] = 0.0f;

    int s = 0;
    uint32_t phase = 0;
#pragma unroll 1
    for (int kt = 0; kt < K_ITERS; kt++) {
        mbar_wait(bar0 + 8 * s, phase);
        uint32_t As = base + s * STAGE_BYTES;
        uint32_t Bs = As + A_TILE_BYTES;
#pragma unroll
        for (int ks = 0; ks < 4; ks++) {
            const uint32_t kb = (uint32_t)ks * 32;
            uint32_t a[4][4];
#pragma unroll
            for (int mb = 0; mb < 4; mb++)
                ldsm4(a[mb], As + a_rowoff + mb * 2048 + ((kb + a_kc) ^ a_xor));
#pragma unroll
            for (int pb = 0; pb < 4; pb++) {
                uint32_t b[4];
                ldsm4(b, Bs + b_rowoff + pb * 2048 + ((kb + b_kc) ^ b_xor));
#pragma unroll
                for (int mb = 0; mb < 4; mb++) {
                    mma16816(acc[mb][2 * pb],     a[mb], b[0], b[1]);
                    mma16816(acc[mb][2 * pb + 1], a[mb], b[2], b[3]);
                }
            }
        }
        // warp done with stage s (ldmatrix is warp-synchronous)
        if (lane == 0) MBARRIER_ARRIVE(bar0 + 8 * (STAGES + s));
        // producer: tid 0 waits for all warps, then refills this stage
        if (tid == 0 && kt + STAGES < K_ITERS) {
            mbar_wait(bar0 + 8 * (STAGES + s), phase);
            int j = kt + STAGES;
            uint32_t full = bar0 + 8 * s;
            MBARRIER_EXPECT_TX(full, (uint32_t)STAGE_BYTES);
            bulk_g2s(base + s * STAGE_BYTES,                gA + (size_t)j * A_TILE_BYTES, A_TILE_BYTES, full);
            bulk_g2s(base + s * STAGE_BYTES + A_TILE_BYTES, gB + (size_t)j * B_TILE_BYTES, B_TILE_BYTES, full);
        }
        if (++s == STAGES) { s = 0; phase ^= 1; }
    }

    // ---- epilogue: direct register -> gmem with bias ----
    const int m0 = mt * M_TILE;
    const int n0 = nt * N_TILE;
    const int col = n0 + warp_n * 64 + (lane & 3) * 2;

    float2 bb[8];
#pragma unroll
    for (int nf = 0; nf < 8; nf++)
        bb[nf] = *reinterpret_cast<const float2*>(bias + col + nf * 8);

#pragma unroll
    for (int mb = 0; mb < 4; mb++) {
        const int r0 = m0 + warp_m * 64 + mb * 16 + (lane >> 2);
        float* p0 = out + (size_t)r0 * OUT_F;
        float* p1 = p0 + (size_t)8 * OUT_F;
#pragma unroll
        for (int nf = 0; nf < 8; nf++) {
            float2 v0, v1;
            v0.x = acc[mb][nf][0] + bb[nf].x;
            v0.y = acc[mb][nf][1] + bb[nf].y;
            v1.x = acc[mb][nf][2] + bb[nf].x;
            v1.y = acc[mb][nf][3] + bb[nf].y;
            *reinterpret_cast<float2*>(p0 + col + nf * 8) = v0;
            *reinterpret_cast<float2*>(p1 + col + nf * 8) = v1;
        }
    }
}

// ---------------- launch ----------------
extern "C" void kernel_launch(void* const* d_in, const int* in_sizes, int n_in,
                              void* d_out, int out_size) {
    const float* x     = (const float*)d_in[0];
    const int*   Wq    = (const int*)  d_in[1];
    const float* scale = (const float*)d_in[2];
    const float* zero  = (const float*)d_in[3];
    const float* bias  = (const float*)d_in[4];
    float* out = (float*)d_out;

    convert_x_kernel<<<(TOKENS * IN_F / 8) / 256, 256>>>(x);
    dequant_w_kernel<<<dim3((G / 8) / 256, RHALF), 256>>>(Wq, scale, zero);

    cudaFuncSetAttribute(gemm_kernel, cudaFuncAttributeMaxDynamicSharedMemorySize, SMEM_DYN);
    gemm_kernel<<<dim3(M_TILES, N_TILES), 128, SMEM_DYN>>>(out, bias);
}